// round 2
// baseline (speedup 1.0000x reference)
#include <cuda_runtime.h>
#include <math.h>

#define SS 64
#define BB 32
#define HH 512
#define EE 512
#define VV 32000
#define LL 2
#define SB (SS*BB)   // 2048

// -------- scratch (no allocation allowed; device globals instead) --------
__device__ float g_x[SB*HH];          // layer input  (4 MB)
__device__ float g_y[SB*HH];          // layer output (4 MB)
__device__ float g_gates[3*SB*HH];    // xr,xz,xh     (12.6 MB)
__device__ float g_h[2][BB*HH];       // ping-pong hidden

// ---------------------------- embedding ---------------------------------
__global__ void embed_kernel(const int* __restrict__ inputs,
                             const float* __restrict__ emb,
                             float* __restrict__ out)
{
    int row = blockIdx.x;                    // row = s*B + b
    int tok = inputs[row];
    const float4* src = (const float4*)(emb + (size_t)tok * EE);
    float4* dst = (float4*)(out + (size_t)row * EE);
    dst[threadIdx.x] = src[threadIdx.x];     // 128 threads * float4 = 512
}

// ------------------------------ copy ------------------------------------
__global__ void copy16k_kernel(const float* __restrict__ src, float* __restrict__ dst)
{
    int i = blockIdx.x * blockDim.x + threadIdx.x;   // 4096 float4
    ((float4*)dst)[i] = ((const float4*)src)[i];
}

// -------------------- fp32 GEMM: C[M,N] = A[M,K] * B[N,K]^T + bias[N] ----
// 128x128 tile, BK=8, 256 threads, 8x8 per thread (split 4+4 for coalesced IO)
__global__ __launch_bounds__(256) void sgemm_nt_bias(
    const float* __restrict__ A, const float* __restrict__ Bm,
    const float* __restrict__ bias, float* __restrict__ C,
    int M, int N, int K)
{
    __shared__ float As[8][128];
    __shared__ float Bs[8][128];

    const int m0 = blockIdx.y * 128;
    const int n0 = blockIdx.x * 128;
    const int tid = threadIdx.x;

    const int lr = tid >> 1;          // 0..127 row-in-tile for loads
    const int lc = (tid & 1) * 4;     // 0 or 4  k-offset for loads
    const int tx = tid & 15;          // n quad group
    const int ty = tid >> 4;          // m quad group

    float acc[8][8];
#pragma unroll
    for (int i = 0; i < 8; ++i)
#pragma unroll
        for (int j = 0; j < 8; ++j) acc[i][j] = 0.f;

    const float* Ag = A  + (size_t)(m0 + lr) * K + lc;
    const float* Bg = Bm + (size_t)(n0 + lr) * K + lc;

    for (int k0 = 0; k0 < K; k0 += 8) {
        float4 a4 = *(const float4*)(Ag + k0);
        float4 b4 = *(const float4*)(Bg + k0);
        As[lc + 0][lr] = a4.x; As[lc + 1][lr] = a4.y;
        As[lc + 2][lr] = a4.z; As[lc + 3][lr] = a4.w;
        Bs[lc + 0][lr] = b4.x; Bs[lc + 1][lr] = b4.y;
        Bs[lc + 2][lr] = b4.z; Bs[lc + 3][lr] = b4.w;
        __syncthreads();

#pragma unroll
        for (int kk = 0; kk < 8; ++kk) {
            float ar[8], br[8];
            *(float4*)&ar[0] = *(const float4*)&As[kk][ty * 4];
            *(float4*)&ar[4] = *(const float4*)&As[kk][ty * 4 + 64];
            *(float4*)&br[0] = *(const float4*)&Bs[kk][tx * 4];
            *(float4*)&br[4] = *(const float4*)&Bs[kk][tx * 4 + 64];
#pragma unroll
            for (int i = 0; i < 8; ++i)
#pragma unroll
                for (int j = 0; j < 8; ++j)
                    acc[i][j] += ar[i] * br[j];
        }
        __syncthreads();
    }

#pragma unroll
    for (int i = 0; i < 8; ++i) {
        int m = m0 + ty * 4 + (i & 3) + (i >> 2) * 64;
#pragma unroll
        for (int jh = 0; jh < 2; ++jh) {
            int n = n0 + tx * 4 + jh * 64;
            float4 v;
            v.x = acc[i][jh * 4 + 0] + bias[n + 0];
            v.y = acc[i][jh * 4 + 1] + bias[n + 1];
            v.z = acc[i][jh * 4 + 2] + bias[n + 2];
            v.w = acc[i][jh * 4 + 3] + bias[n + 3];
            *(float4*)&C[(size_t)m * N + n] = v;
        }
    }
}

// ----------------------------- GRU step ---------------------------------
// grid 128 blocks (4 j's each), 128 threads: tx=b(0..31), ty=local j(0..3).
// SMEM: full h transposed [512][33] (conflict-free), 12 weight rows [12][512].
__global__ __launch_bounds__(128) void gru_step_kernel(
    const float* __restrict__ gates,   // [3][SB][H] base
    const float* __restrict__ Whr,
    const float* __restrict__ Whz,
    const float* __restrict__ Whh,
    const float* __restrict__ h_in,    // [B][H]
    float* __restrict__ h_out,         // [B][H]
    float* __restrict__ hs_out,        // already offset to step s: [B][H]
    float* __restrict__ hfin,          // may be null
    int s)
{
    extern __shared__ float smem[];
    float* hsm = smem;                 // [512][33]
    float* wsm = smem + HH * 33;       // [12][512]
    const int tid = threadIdx.x;

    // stage h: coalesced global read, padded transpose into smem
#pragma unroll
    for (int it = 0; it < (BB * HH) / 128; ++it) {
        int f = tid + it * 128;
        int b = f >> 9;
        int k = f & (HH - 1);
        hsm[k * 33 + b] = h_in[f];
    }
    // stage 4 rows of each recurrent weight matrix
    const int jbase = blockIdx.x * 4;
    const float* Ws[3] = {Whr, Whz, Whh};
#pragma unroll
    for (int g = 0; g < 3; ++g)
#pragma unroll
        for (int jj = 0; jj < 4; ++jj)
            ((float4*)(wsm + (g * 4 + jj) * HH))[tid] =
                ((const float4*)(Ws[g] + (size_t)(jbase + jj) * HH))[tid];
    __syncthreads();

    const int tx = tid & 31;   // b
    const int ty = tid >> 5;   // local j
    const float4* wr4 = (const float4*)(wsm + (0 * 4 + ty) * HH);
    const float4* wz4 = (const float4*)(wsm + (1 * 4 + ty) * HH);
    const float4* wh4 = (const float4*)(wsm + (2 * 4 + ty) * HH);

    float accr = 0.f, accz = 0.f, acch = 0.f;
#pragma unroll 8
    for (int k4 = 0; k4 < HH / 4; ++k4) {
        float4 a = wr4[k4];
        float4 bz = wz4[k4];
        float4 c = wh4[k4];
        int kb = k4 * 4;
        float h0 = hsm[(kb + 0) * 33 + tx];
        float h1 = hsm[(kb + 1) * 33 + tx];
        float h2 = hsm[(kb + 2) * 33 + tx];
        float h3 = hsm[(kb + 3) * 33 + tx];
        accr += a.x * h0 + a.y * h1 + a.z * h2 + a.w * h3;
        accz += bz.x * h0 + bz.y * h1 + bz.z * h2 + bz.w * h3;
        acch += c.x * h0 + c.y * h1 + c.z * h2 + c.w * h3;
    }

    const int j = jbase + ty;
    const int row = s * BB + tx;
    float xr = gates[(size_t)row * HH + j];
    float xz = gates[(size_t)SB * HH + (size_t)row * HH + j];
    float xh = gates[(size_t)2 * SB * HH + (size_t)row * HH + j];
    float hold = hsm[j * 33 + tx];

    float r  = 1.f / (1.f + expf(-(xr + accr)));
    float z  = 1.f / (1.f + expf(-(xz + accz)));
    float h1c = tanhf(xh + r * acch);
    float hn = (1.f - z) * h1c + z * hold;

    h_out[tx * HH + j]  = hn;
    hs_out[tx * HH + j] = hn;
    if (hfin) hfin[tx * HH + j] = hn;
}

// ------------------------------ driver ----------------------------------
extern "C" void kernel_launch(void* const* d_in, const int* in_sizes, int n_in,
                              void* d_out, int out_size)
{
    const int*   inputs = (const int*)d_in[0];
    const float* hidden = (const float*)d_in[1];
    const float* emb    = (const float*)d_in[2];
    const float* Wir    = (const float*)d_in[3];
    const float* bir    = (const float*)d_in[4];
    const float* Wiz    = (const float*)d_in[5];
    const float* biz    = (const float*)d_in[6];
    const float* Wih    = (const float*)d_in[7];
    const float* bih    = (const float*)d_in[8];
    const float* Whr    = (const float*)d_in[9];
    const float* Whz    = (const float*)d_in[10];
    const float* Whh    = (const float*)d_in[11];
    const float* Wout   = (const float*)d_in[12];
    const float* bout   = (const float*)d_in[13];
    float* out = (float*)d_out;

    float *px, *py, *pg, *ph0, *ph1;
    cudaGetSymbolAddress((void**)&px, g_x);
    cudaGetSymbolAddress((void**)&py, g_y);
    cudaGetSymbolAddress((void**)&pg, g_gates);
    cudaGetSymbolAddress((void**)&ph0, g_h);
    ph1 = ph0 + BB * HH;

    const size_t logits_elems = (size_t)SB * VV;
    float* hfin_base = nullptr;
    if ((size_t)out_size >= logits_elems + (size_t)LL * BB * HH)
        hfin_base = out + logits_elems;

    const int smem_step = (HH * 33 + 12 * HH) * sizeof(float);  // 92160 B
    cudaFuncSetAttribute(gru_step_kernel,
                         cudaFuncAttributeMaxDynamicSharedMemorySize, smem_step);

    // 1) embedding
    embed_kernel<<<SB, 128>>>(inputs, emb, px);

    const size_t CHNK = (size_t)SB * HH;
    for (int l = 0; l < LL; ++l) {
        float* in  = (l == 0) ? px : py;
        float* outb = (l == 0) ? py : px;

        // 2) batched input projections (3 GEMMs, [2048,512]x[512,512]^T)
        dim3 gProj(EE / 128, SB / 128);  // (4, 16)
        sgemm_nt_bias<<<gProj, 256>>>(in, Wir + (size_t)l * HH * EE,
                                      bir + l * HH, pg + 0 * CHNK, SB, HH, EE);
        sgemm_nt_bias<<<gProj, 256>>>(in, Wiz + (size_t)l * HH * EE,
                                      biz + l * HH, pg + 1 * CHNK, SB, HH, EE);
        sgemm_nt_bias<<<gProj, 256>>>(in, Wih + (size_t)l * HH * EE,
                                      bih + l * HH, pg + 2 * CHNK, SB, HH, EE);

        // 3) init hidden
        copy16k_kernel<<<32, 128>>>(hidden + (size_t)l * BB * HH, ph0);

        // 4) sequential scan
        const float* whr = Whr + (size_t)l * HH * HH;
        const float* whz = Whz + (size_t)l * HH * HH;
        const float* whh = Whh + (size_t)l * HH * HH;
        for (int s = 0; s < SS; ++s) {
            float* hin  = (s & 1) ? ph1 : ph0;
            float* hout = (s & 1) ? ph0 : ph1;
            float* hf = (s == SS - 1 && hfin_base)
                            ? hfin_base + (size_t)l * BB * HH : nullptr;
            gru_step_kernel<<<128, 128, smem_step>>>(
                pg, whr, whz, whh, hin, hout,
                outb + (size_t)s * BB * HH, hf, s);
        }
    }

    // 5) logits GEMM: [2048,512] x [32000,512]^T + bout -> out
    dim3 gLog(VV / 128, SB / 128);  // (250, 16)
    sgemm_nt_bias<<<gLog, 256>>>(px, Wout, bout, out, SB, VV, EE);
}

// round 3
// speedup vs baseline: 1.6011x; 1.6011x over previous
#include <cuda_runtime.h>
#include <math.h>

#define SS 64
#define BB 32
#define HH 512
#define EE 512
#define VV 32000
#define LL 2
#define SB (SS*BB)   // 2048

// -------- scratch (no allocation allowed; device globals instead) --------
__device__ float g_x[SB*HH];          // layer input  (4 MB)
__device__ float g_y[SB*HH];          // layer output (4 MB)
__device__ float g_gates[3*SB*HH];    // xr,xz,xh     (12.6 MB)
__device__ float g_h[2][BB*HH];       // ping-pong hidden

// ---------------------------- embedding ---------------------------------
__global__ void embed_kernel(const int* __restrict__ inputs,
                             const float* __restrict__ emb,
                             float* __restrict__ out)
{
    int row = blockIdx.x;                    // row = s*B + b
    int tok = inputs[row];
    const float4* src = (const float4*)(emb + (size_t)tok * EE);
    float4* dst = (float4*)(out + (size_t)row * EE);
    dst[threadIdx.x] = src[threadIdx.x];     // 128 threads * float4 = 512
}

// ------------------------------ copy ------------------------------------
__global__ void copy16k_kernel(const float* __restrict__ src, float* __restrict__ dst)
{
    int i = blockIdx.x * blockDim.x + threadIdx.x;   // 4096 float4
    ((float4*)dst)[i] = ((const float4*)src)[i];
}

// -------------------- fp32 GEMM (projections, z-fused over 3 gates) -----
// C[M,N] = A[M,K] * B[N,K]^T + bias[N]; 128x128 tile, BK=8, 256 thr, 8x8/thr
__global__ __launch_bounds__(256) void sgemm_nt_bias3(
    const float* __restrict__ A,
    const float* __restrict__ W0, const float* __restrict__ W1, const float* __restrict__ W2,
    const float* __restrict__ b0, const float* __restrict__ b1, const float* __restrict__ b2,
    float* __restrict__ C0, float* __restrict__ C1, float* __restrict__ C2,
    int M, int N, int K)
{
    const float* Bm  = (blockIdx.z == 0) ? W0 : (blockIdx.z == 1) ? W1 : W2;
    const float* bias = (blockIdx.z == 0) ? b0 : (blockIdx.z == 1) ? b1 : b2;
    float* C         = (blockIdx.z == 0) ? C0 : (blockIdx.z == 1) ? C1 : C2;

    __shared__ float As[8][128];
    __shared__ float Bs[8][128];

    const int m0 = blockIdx.y * 128;
    const int n0 = blockIdx.x * 128;
    const int tid = threadIdx.x;

    const int lr = tid >> 1;
    const int lc = (tid & 1) * 4;
    const int tx = tid & 15;
    const int ty = tid >> 4;

    float acc[8][8];
#pragma unroll
    for (int i = 0; i < 8; ++i)
#pragma unroll
        for (int j = 0; j < 8; ++j) acc[i][j] = 0.f;

    const float* Ag = A  + (size_t)(m0 + lr) * K + lc;
    const float* Bg = Bm + (size_t)(n0 + lr) * K + lc;

    for (int k0 = 0; k0 < K; k0 += 8) {
        float4 a4 = *(const float4*)(Ag + k0);
        float4 b4 = *(const float4*)(Bg + k0);
        As[lc + 0][lr] = a4.x; As[lc + 1][lr] = a4.y;
        As[lc + 2][lr] = a4.z; As[lc + 3][lr] = a4.w;
        Bs[lc + 0][lr] = b4.x; Bs[lc + 1][lr] = b4.y;
        Bs[lc + 2][lr] = b4.z; Bs[lc + 3][lr] = b4.w;
        __syncthreads();

#pragma unroll
        for (int kk = 0; kk < 8; ++kk) {
            float ar[8], br[8];
            *(float4*)&ar[0] = *(const float4*)&As[kk][ty * 4];
            *(float4*)&ar[4] = *(const float4*)&As[kk][ty * 4 + 64];
            *(float4*)&br[0] = *(const float4*)&Bs[kk][tx * 4];
            *(float4*)&br[4] = *(const float4*)&Bs[kk][tx * 4 + 64];
#pragma unroll
            for (int i = 0; i < 8; ++i)
#pragma unroll
                for (int j = 0; j < 8; ++j)
                    acc[i][j] += ar[i] * br[j];
        }
        __syncthreads();
    }

#pragma unroll
    for (int i = 0; i < 8; ++i) {
        int m = m0 + ty * 4 + (i & 3) + (i >> 2) * 64;
#pragma unroll
        for (int jh = 0; jh < 2; ++jh) {
            int n = n0 + tx * 4 + jh * 64;
            float4 v;
            v.x = acc[i][jh * 4 + 0] + bias[n + 0];
            v.y = acc[i][jh * 4 + 1] + bias[n + 1];
            v.z = acc[i][jh * 4 + 2] + bias[n + 2];
            v.w = acc[i][jh * 4 + 3] + bias[n + 3];
            *(float4*)&C[(size_t)m * N + n] = v;
        }
    }
}

// ------------------ tf32 tensor-core GEMM for logits ---------------------
// C[M,N] = A[M,K]*W[N,K]^T + bias. BM=BN=128, BK=16, 4 warps of 64x64.
// smem: 16B-chunk XOR swizzle -> conflict-free STS.128, <=2-way LDS.32.
__device__ __forceinline__ unsigned f2tf(float x)
{
    unsigned r;
    asm("cvt.rna.tf32.f32 %0, %1;" : "=r"(r) : "f"(x));
    return r;
}

__global__ __launch_bounds__(128) void gemm_tf32_nt_bias(
    const float* __restrict__ A, const float* __restrict__ W,
    const float* __restrict__ bias, float* __restrict__ C,
    int M, int N, int K)
{
    __shared__ unsigned As[2][128 * 16];
    __shared__ unsigned Bs[2][128 * 16];

    const int tid  = threadIdx.x;
    const int lane = tid & 31;
    const int warp = tid >> 5;
    const int wm = (warp >> 1) * 64;
    const int wn = (warp & 1) * 64;
    const int m0 = blockIdx.y * 128;
    const int n0 = blockIdx.x * 128;

    const int fr = lane >> 2;   // 0..7
    const int fc = lane & 3;    // 0..3

    const int cm  = tid >> 2;   // copy row within 32-row slab
    const int cc2 = tid & 3;    // which 16B chunk of the 16-k row

    float acc[4][8][4];
#pragma unroll
    for (int mt = 0; mt < 4; ++mt)
#pragma unroll
        for (int nt = 0; nt < 8; ++nt)
#pragma unroll
            for (int q = 0; q < 4; ++q) acc[mt][nt][q] = 0.f;

    float4 ra[4], rb[4];

#define LD_STAGE(k0)                                                          \
    {                                                                         \
        _Pragma("unroll")                                                     \
        for (int i = 0; i < 4; ++i) {                                         \
            int m = i * 32 + cm;                                              \
            ra[i] = *(const float4*)&A[(size_t)(m0 + m) * K + (k0) + cc2*4];  \
            rb[i] = *(const float4*)&W[(size_t)(n0 + m) * K + (k0) + cc2*4];  \
        }                                                                     \
    }

#define ST_STAGE(buf)                                                         \
    {                                                                         \
        _Pragma("unroll")                                                     \
        for (int i = 0; i < 4; ++i) {                                         \
            int m = i * 32 + cm;                                              \
            int off = m * 16 + ((cc2 ^ (m & 3)) << 2);                        \
            uint4 ua; ua.x = f2tf(ra[i].x); ua.y = f2tf(ra[i].y);             \
            ua.z = f2tf(ra[i].z); ua.w = f2tf(ra[i].w);                       \
            uint4 ub; ub.x = f2tf(rb[i].x); ub.y = f2tf(rb[i].y);             \
            ub.z = f2tf(rb[i].z); ub.w = f2tf(rb[i].w);                       \
            *(uint4*)&As[buf][off] = ua;                                      \
            *(uint4*)&Bs[buf][off] = ub;                                      \
        }                                                                     \
    }

    LD_STAGE(0);
    ST_STAGE(0);
    __syncthreads();

    const int nstages = K / 16;
    for (int s = 0; s < nstages; ++s) {
        const int buf = s & 1;
        if (s + 1 < nstages) LD_STAGE((s + 1) * 16);

        // ----- compute current stage (2 k8 sub-steps) -----
#pragma unroll
        for (int k8 = 0; k8 < 2; ++k8) {
            unsigned af[4][4], bf[8][2];
#pragma unroll
            for (int mt = 0; mt < 4; ++mt) {
                int r1 = wm + mt * 16 + fr;
                int r2 = r1 + 8;
                af[mt][0] = As[buf][r1*16 + (((k8*2+0) ^ (r1&3)) << 2) + fc];
                af[mt][1] = As[buf][r2*16 + (((k8*2+0) ^ (r2&3)) << 2) + fc];
                af[mt][2] = As[buf][r1*16 + (((k8*2+1) ^ (r1&3)) << 2) + fc];
                af[mt][3] = As[buf][r2*16 + (((k8*2+1) ^ (r2&3)) << 2) + fc];
            }
#pragma unroll
            for (int nt = 0; nt < 8; ++nt) {
                int n = wn + nt * 8 + fr;
                bf[nt][0] = Bs[buf][n*16 + (((k8*2+0) ^ (n&3)) << 2) + fc];
                bf[nt][1] = Bs[buf][n*16 + (((k8*2+1) ^ (n&3)) << 2) + fc];
            }
#pragma unroll
            for (int mt = 0; mt < 4; ++mt)
#pragma unroll
                for (int nt = 0; nt < 8; ++nt) {
                    asm volatile(
                        "mma.sync.aligned.m16n8k8.row.col.f32.tf32.tf32.f32 "
                        "{%0,%1,%2,%3}, {%4,%5,%6,%7}, {%8,%9}, {%0,%1,%2,%3};"
                        : "+f"(acc[mt][nt][0]), "+f"(acc[mt][nt][1]),
                          "+f"(acc[mt][nt][2]), "+f"(acc[mt][nt][3])
                        : "r"(af[mt][0]), "r"(af[mt][1]),
                          "r"(af[mt][2]), "r"(af[mt][3]),
                          "r"(bf[nt][0]), "r"(bf[nt][1]));
                }
        }

        if (s + 1 < nstages) ST_STAGE(buf ^ 1);
        __syncthreads();
    }
#undef LD_STAGE
#undef ST_STAGE

    // ----- epilogue -----
#pragma unroll
    for (int mt = 0; mt < 4; ++mt) {
        int row = m0 + wm + mt * 16 + fr;
#pragma unroll
        for (int nt = 0; nt < 8; ++nt) {
            int col = n0 + wn + nt * 8 + fc * 2;
            float bv0 = bias[col], bv1 = bias[col + 1];
            float2 v0; v0.x = acc[mt][nt][0] + bv0; v0.y = acc[mt][nt][1] + bv1;
            float2 v1; v1.x = acc[mt][nt][2] + bv0; v1.y = acc[mt][nt][3] + bv1;
            *(float2*)&C[(size_t)row * N + col] = v0;
            *(float2*)&C[(size_t)(row + 8) * N + col] = v1;
        }
    }
}

// ----------------------------- GRU step ---------------------------------
__global__ __launch_bounds__(128) void gru_step_kernel(
    const float* __restrict__ gates,
    const float* __restrict__ Whr,
    const float* __restrict__ Whz,
    const float* __restrict__ Whh,
    const float* __restrict__ h_in,
    float* __restrict__ h_out,
    float* __restrict__ hs_out,
    float* __restrict__ hfin,
    int s)
{
    extern __shared__ float smem[];
    float* hsm = smem;                 // [512][33]
    float* wsm = smem + HH * 33;       // [12][512]
    const int tid = threadIdx.x;

#pragma unroll
    for (int it = 0; it < (BB * HH) / 128; ++it) {
        int f = tid + it * 128;
        int b = f >> 9;
        int k = f & (HH - 1);
        hsm[k * 33 + b] = h_in[f];
    }
    const int jbase = blockIdx.x * 4;
    const float* Ws[3] = {Whr, Whz, Whh};
#pragma unroll
    for (int g = 0; g < 3; ++g)
#pragma unroll
        for (int jj = 0; jj < 4; ++jj)
            ((float4*)(wsm + (g * 4 + jj) * HH))[tid] =
                ((const float4*)(Ws[g] + (size_t)(jbase + jj) * HH))[tid];
    __syncthreads();

    const int tx = tid & 31;
    const int ty = tid >> 5;
    const float4* wr4 = (const float4*)(wsm + (0 * 4 + ty) * HH);
    const float4* wz4 = (const float4*)(wsm + (1 * 4 + ty) * HH);
    const float4* wh4 = (const float4*)(wsm + (2 * 4 + ty) * HH);

    float accr = 0.f, accz = 0.f, acch = 0.f;
#pragma unroll 8
    for (int k4 = 0; k4 < HH / 4; ++k4) {
        float4 a = wr4[k4];
        float4 bz = wz4[k4];
        float4 c = wh4[k4];
        int kb = k4 * 4;
        float h0 = hsm[(kb + 0) * 33 + tx];
        float h1 = hsm[(kb + 1) * 33 + tx];
        float h2 = hsm[(kb + 2) * 33 + tx];
        float h3 = hsm[(kb + 3) * 33 + tx];
        accr += a.x * h0 + a.y * h1 + a.z * h2 + a.w * h3;
        accz += bz.x * h0 + bz.y * h1 + bz.z * h2 + bz.w * h3;
        acch += c.x * h0 + c.y * h1 + c.z * h2 + c.w * h3;
    }

    const int j = jbase + ty;
    const int row = s * BB + tx;
    float xr = gates[(size_t)row * HH + j];
    float xz = gates[(size_t)SB * HH + (size_t)row * HH + j];
    float xh = gates[(size_t)2 * SB * HH + (size_t)row * HH + j];
    float hold = hsm[j * 33 + tx];

    float r  = 1.f / (1.f + expf(-(xr + accr)));
    float z  = 1.f / (1.f + expf(-(xz + accz)));
    float h1c = tanhf(xh + r * acch);
    float hn = (1.f - z) * h1c + z * hold;

    h_out[tx * HH + j]  = hn;
    hs_out[tx * HH + j] = hn;
    if (hfin) hfin[tx * HH + j] = hn;
}

// ------------------------------ driver ----------------------------------
extern "C" void kernel_launch(void* const* d_in, const int* in_sizes, int n_in,
                              void* d_out, int out_size)
{
    const int*   inputs = (const int*)d_in[0];
    const float* hidden = (const float*)d_in[1];
    const float* emb    = (const float*)d_in[2];
    const float* Wir    = (const float*)d_in[3];
    const float* bir    = (const float*)d_in[4];
    const float* Wiz    = (const float*)d_in[5];
    const float* biz    = (const float*)d_in[6];
    const float* Wih    = (const float*)d_in[7];
    const float* bih    = (const float*)d_in[8];
    const float* Whr    = (const float*)d_in[9];
    const float* Whz    = (const float*)d_in[10];
    const float* Whh    = (const float*)d_in[11];
    const float* Wout   = (const float*)d_in[12];
    const float* bout   = (const float*)d_in[13];
    float* out = (float*)d_out;

    float *px, *py, *pg, *ph0, *ph1;
    cudaGetSymbolAddress((void**)&px, g_x);
    cudaGetSymbolAddress((void**)&py, g_y);
    cudaGetSymbolAddress((void**)&pg, g_gates);
    cudaGetSymbolAddress((void**)&ph0, g_h);
    ph1 = ph0 + BB * HH;

    const size_t logits_elems = (size_t)SB * VV;
    float* hfin_base = nullptr;
    if ((size_t)out_size >= logits_elems + (size_t)LL * BB * HH)
        hfin_base = out + logits_elems;

    const int smem_step = (HH * 33 + 12 * HH) * sizeof(float);  // 92160 B
    cudaFuncSetAttribute(gru_step_kernel,
                         cudaFuncAttributeMaxDynamicSharedMemorySize, smem_step);

    // 1) embedding
    embed_kernel<<<SB, 128>>>(inputs, emb, px);

    const size_t CHNK = (size_t)SB * HH;
    for (int l = 0; l < LL; ++l) {
        float* in   = (l == 0) ? px : py;
        float* outb = (l == 0) ? py : px;

        // 2) fused input projections: one launch, 3 gates via grid.z
        dim3 gProj(EE / 128, SB / 128, 3);  // (4, 16, 3) = 192 blocks
        sgemm_nt_bias3<<<gProj, 256>>>(
            in,
            Wir + (size_t)l * HH * EE, Wiz + (size_t)l * HH * EE, Wih + (size_t)l * HH * EE,
            bir + l * HH, biz + l * HH, bih + l * HH,
            pg + 0 * CHNK, pg + 1 * CHNK, pg + 2 * CHNK,
            SB, HH, EE);

        // 3) init hidden
        copy16k_kernel<<<32, 128>>>(hidden + (size_t)l * BB * HH, ph0);

        // 4) sequential scan
        const float* whr = Whr + (size_t)l * HH * HH;
        const float* whz = Whz + (size_t)l * HH * HH;
        const float* whh = Whh + (size_t)l * HH * HH;
        for (int s = 0; s < SS; ++s) {
            float* hin  = (s & 1) ? ph1 : ph0;
            float* hout = (s & 1) ? ph0 : ph1;
            float* hf = (s == SS - 1 && hfin_base)
                            ? hfin_base + (size_t)l * BB * HH : nullptr;
            gru_step_kernel<<<128, 128, smem_step>>>(
                pg, whr, whz, whh, hin, hout,
                outb + (size_t)s * BB * HH, hf, s);
        }
    }

    // 5) logits GEMM via tf32 tensor cores
    dim3 gLog(VV / 128, SB / 128);  // (250, 16)
    gemm_tf32_nt_bias<<<gLog, 128>>>(px, Wout, bout, out, SB, VV, EE);
}

// round 4
// speedup vs baseline: 2.1568x; 1.3471x over previous
#include <cuda_runtime.h>
#include <math.h>

#define SS 64
#define BB 32
#define HH 512
#define EE 512
#define VV 32000
#define LL 2
#define SB (SS*BB)   // 2048
#define NBLK 128
#define HSTRIDE 520  // 512 + 8 pad (float4-aligned)

// -------- scratch (no allocation allowed; device globals instead) --------
__device__ float g_x[SB*HH];
__device__ float g_y[SB*HH];
__device__ float g_gates[3*SB*HH];
__device__ float g_h[2*BB*HH];        // ping-pong hidden
__device__ unsigned g_cnt;            // zero-init
__device__ volatile unsigned g_sense; // zero-init; even #barriers/launch -> returns to 0

// ---------------------------- embedding ---------------------------------
__global__ void embed_kernel(const int* __restrict__ inputs,
                             const float* __restrict__ emb,
                             float* __restrict__ out)
{
    int row = blockIdx.x;
    int tok = inputs[row];
    const float4* src = (const float4*)(emb + (size_t)tok * EE);
    float4* dst = (float4*)(out + (size_t)row * EE);
    dst[threadIdx.x] = src[threadIdx.x];
}

// -------------------- fp32 GEMM (projections, z-fused over 3 gates) -----
__global__ __launch_bounds__(256) void sgemm_nt_bias3(
    const float* __restrict__ A,
    const float* __restrict__ W0, const float* __restrict__ W1, const float* __restrict__ W2,
    const float* __restrict__ b0, const float* __restrict__ b1, const float* __restrict__ b2,
    float* __restrict__ C0, float* __restrict__ C1, float* __restrict__ C2,
    int M, int N, int K)
{
    const float* Bm   = (blockIdx.z == 0) ? W0 : (blockIdx.z == 1) ? W1 : W2;
    const float* bias = (blockIdx.z == 0) ? b0 : (blockIdx.z == 1) ? b1 : b2;
    float* C          = (blockIdx.z == 0) ? C0 : (blockIdx.z == 1) ? C1 : C2;

    __shared__ float As[8][128];
    __shared__ float Bs[8][128];

    const int m0 = blockIdx.y * 128;
    const int n0 = blockIdx.x * 128;
    const int tid = threadIdx.x;
    const int lr = tid >> 1;
    const int lc = (tid & 1) * 4;
    const int tx = tid & 15;
    const int ty = tid >> 4;

    float acc[8][8];
#pragma unroll
    for (int i = 0; i < 8; ++i)
#pragma unroll
        for (int j = 0; j < 8; ++j) acc[i][j] = 0.f;

    const float* Ag = A  + (size_t)(m0 + lr) * K + lc;
    const float* Bg = Bm + (size_t)(n0 + lr) * K + lc;

    for (int k0 = 0; k0 < K; k0 += 8) {
        float4 a4 = *(const float4*)(Ag + k0);
        float4 b4 = *(const float4*)(Bg + k0);
        As[lc + 0][lr] = a4.x; As[lc + 1][lr] = a4.y;
        As[lc + 2][lr] = a4.z; As[lc + 3][lr] = a4.w;
        Bs[lc + 0][lr] = b4.x; Bs[lc + 1][lr] = b4.y;
        Bs[lc + 2][lr] = b4.z; Bs[lc + 3][lr] = b4.w;
        __syncthreads();
#pragma unroll
        for (int kk = 0; kk < 8; ++kk) {
            float ar[8], br[8];
            *(float4*)&ar[0] = *(const float4*)&As[kk][ty * 4];
            *(float4*)&ar[4] = *(const float4*)&As[kk][ty * 4 + 64];
            *(float4*)&br[0] = *(const float4*)&Bs[kk][tx * 4];
            *(float4*)&br[4] = *(const float4*)&Bs[kk][tx * 4 + 64];
#pragma unroll
            for (int i = 0; i < 8; ++i)
#pragma unroll
                for (int j = 0; j < 8; ++j)
                    acc[i][j] += ar[i] * br[j];
        }
        __syncthreads();
    }
#pragma unroll
    for (int i = 0; i < 8; ++i) {
        int m = m0 + ty * 4 + (i & 3) + (i >> 2) * 64;
#pragma unroll
        for (int jh = 0; jh < 2; ++jh) {
            int n = n0 + tx * 4 + jh * 64;
            float4 v;
            v.x = acc[i][jh * 4 + 0] + bias[n + 0];
            v.y = acc[i][jh * 4 + 1] + bias[n + 1];
            v.z = acc[i][jh * 4 + 2] + bias[n + 2];
            v.w = acc[i][jh * 4 + 3] + bias[n + 3];
            *(float4*)&C[(size_t)m * N + n] = v;
        }
    }
}

// ------------------ tf32 tensor-core GEMM for logits ---------------------
__device__ __forceinline__ unsigned f2tf(float x)
{
    unsigned r;
    asm("cvt.rna.tf32.f32 %0, %1;" : "=r"(r) : "f"(x));
    return r;
}

__global__ __launch_bounds__(128) void gemm_tf32_nt_bias(
    const float* __restrict__ A, const float* __restrict__ W,
    const float* __restrict__ bias, float* __restrict__ C,
    int M, int N, int K)
{
    __shared__ unsigned As[2][128 * 16];
    __shared__ unsigned Bs[2][128 * 16];

    const int tid  = threadIdx.x;
    const int lane = tid & 31;
    const int warp = tid >> 5;
    const int wm = (warp >> 1) * 64;
    const int wn = (warp & 1) * 64;
    const int m0 = blockIdx.y * 128;
    const int n0 = blockIdx.x * 128;
    const int fr = lane >> 2;
    const int fc = lane & 3;
    const int cm  = tid >> 2;
    const int cc2 = tid & 3;

    float acc[4][8][4];
#pragma unroll
    for (int mt = 0; mt < 4; ++mt)
#pragma unroll
        for (int nt = 0; nt < 8; ++nt)
#pragma unroll
            for (int q = 0; q < 4; ++q) acc[mt][nt][q] = 0.f;

    float4 ra[4], rb[4];

#define LD_STAGE(k0)                                                          \
    {                                                                         \
        _Pragma("unroll")                                                     \
        for (int i = 0; i < 4; ++i) {                                         \
            int m = i * 32 + cm;                                              \
            ra[i] = *(const float4*)&A[(size_t)(m0 + m) * K + (k0) + cc2*4];  \
            rb[i] = *(const float4*)&W[(size_t)(n0 + m) * K + (k0) + cc2*4];  \
        }                                                                     \
    }

#define ST_STAGE(buf)                                                         \
    {                                                                         \
        _Pragma("unroll")                                                     \
        for (int i = 0; i < 4; ++i) {                                         \
            int m = i * 32 + cm;                                              \
            int off = m * 16 + ((cc2 ^ (m & 3)) << 2);                        \
            uint4 ua; ua.x = f2tf(ra[i].x); ua.y = f2tf(ra[i].y);             \
            ua.z = f2tf(ra[i].z); ua.w = f2tf(ra[i].w);                       \
            uint4 ub; ub.x = f2tf(rb[i].x); ub.y = f2tf(rb[i].y);             \
            ub.z = f2tf(rb[i].z); ub.w = f2tf(rb[i].w);                       \
            *(uint4*)&As[buf][off] = ua;                                      \
            *(uint4*)&Bs[buf][off] = ub;                                      \
        }                                                                     \
    }

    LD_STAGE(0);
    ST_STAGE(0);
    __syncthreads();

    const int nstages = K / 16;
    for (int s = 0; s < nstages; ++s) {
        const int buf = s & 1;
        if (s + 1 < nstages) LD_STAGE((s + 1) * 16);

#pragma unroll
        for (int k8 = 0; k8 < 2; ++k8) {
            unsigned af[4][4], bf[8][2];
#pragma unroll
            for (int mt = 0; mt < 4; ++mt) {
                int r1 = wm + mt * 16 + fr;
                int r2 = r1 + 8;
                af[mt][0] = As[buf][r1*16 + (((k8*2+0) ^ (r1&3)) << 2) + fc];
                af[mt][1] = As[buf][r2*16 + (((k8*2+0) ^ (r2&3)) << 2) + fc];
                af[mt][2] = As[buf][r1*16 + (((k8*2+1) ^ (r1&3)) << 2) + fc];
                af[mt][3] = As[buf][r2*16 + (((k8*2+1) ^ (r2&3)) << 2) + fc];
            }
#pragma unroll
            for (int nt = 0; nt < 8; ++nt) {
                int n = wn + nt * 8 + fr;
                bf[nt][0] = Bs[buf][n*16 + (((k8*2+0) ^ (n&3)) << 2) + fc];
                bf[nt][1] = Bs[buf][n*16 + (((k8*2+1) ^ (n&3)) << 2) + fc];
            }
#pragma unroll
            for (int mt = 0; mt < 4; ++mt)
#pragma unroll
                for (int nt = 0; nt < 8; ++nt) {
                    asm volatile(
                        "mma.sync.aligned.m16n8k8.row.col.f32.tf32.tf32.f32 "
                        "{%0,%1,%2,%3}, {%4,%5,%6,%7}, {%8,%9}, {%0,%1,%2,%3};"
                        : "+f"(acc[mt][nt][0]), "+f"(acc[mt][nt][1]),
                          "+f"(acc[mt][nt][2]), "+f"(acc[mt][nt][3])
                        : "r"(af[mt][0]), "r"(af[mt][1]),
                          "r"(af[mt][2]), "r"(af[mt][3]),
                          "r"(bf[nt][0]), "r"(bf[nt][1]));
                }
        }
        if (s + 1 < nstages) ST_STAGE(buf ^ 1);
        __syncthreads();
    }
#undef LD_STAGE
#undef ST_STAGE

#pragma unroll
    for (int mt = 0; mt < 4; ++mt) {
        int row = m0 + wm + mt * 16 + fr;
#pragma unroll
        for (int nt = 0; nt < 8; ++nt) {
            int col = n0 + wn + nt * 8 + fc * 2;
            float bv0 = bias[col], bv1 = bias[col + 1];
            float2 v0; v0.x = acc[mt][nt][0] + bv0; v0.y = acc[mt][nt][1] + bv1;
            float2 v1; v1.x = acc[mt][nt][2] + bv0; v1.y = acc[mt][nt][3] + bv1;
            *(float2*)&C[(size_t)row * N + col] = v0;
            *(float2*)&C[(size_t)(row + 8) * N + col] = v1;
        }
    }
}

// ------------------ persistent GRU scan (one launch per layer) ----------
// grid=128 blocks (all resident), 256 threads. Block owns j in [4*bid,4*bid+4).
// Warp w: jg=w>>2 (j-pair), bg=w&3 (8 batches). Lane k-slice: k=4*lane+128*i.
// Weights in SMEM once; h ping-pong via global (.cg loads); spin grid barrier.
__global__ __launch_bounds__(256, 1) void gru_scan_kernel(
    const float* __restrict__ gates,   // [3][SB][HH]
    const float* __restrict__ Wr,
    const float* __restrict__ Wz,
    const float* __restrict__ Wh,
    const float* __restrict__ h0,      // [BB][HH]
    float* __restrict__ hb,            // ping-pong [2][BB][HH]
    float* __restrict__ hs_out,        // [SS][BB][HH]
    float* __restrict__ hfin)          // [BB][HH] or null
{
    extern __shared__ float sm[];
    float* hsm = sm;                          // [32][HSTRIDE]
    float* wsm = sm + BB * HSTRIDE;           // [12][512]
    float* red = wsm + 12 * HH;               // [8][48][33]

    const int tid  = threadIdx.x;
    const int lane = tid & 31;
    const int w    = tid >> 5;
    const int jg   = w >> 2;
    const int bg   = w & 3;
    const int bid  = blockIdx.x;

    // ---- load 12 weight rows to smem once ----
    for (int c = tid; c < 12 * HH / 4; c += 256) {
        int r  = c / (HH / 4);
        int kq = c % (HH / 4);
        int g = r >> 2, jl = r & 3;
        const float* W = (g == 0) ? Wr : (g == 1) ? Wz : Wh;
        *(float4*)&wsm[r * HH + kq * 4] =
            *(const float4*)&W[(size_t)(bid * 4 + jl) * HH + kq * 4];
    }

    unsigned local_sense = 0;
    const int jj = lane >> 3;          // valid for lane<16
    const int bb16 = lane & 7;
    const int j = bid * 4 + jg * 2 + jj;
    const int b = bg * 8 + bb16;

    for (int s = 0; s < SS; ++s) {
        const float* hsrc = (s == 0) ? h0 : hb + ((s - 1) & 1) * BB * HH;
        float* hdst = hb + (s & 1) * BB * HH;

        // prefetch gate values for this (j,b)
        float xr = 0.f, xz = 0.f, xh = 0.f;
        if (lane < 16) {
            size_t idx = (size_t)(s * BB + b) * HH + j;
            xr = __ldcg(&gates[idx]);
            xz = __ldcg(&gates[(size_t)SB * HH + idx]);
            xh = __ldcg(&gates[(size_t)2 * SB * HH + idx]);
        }

        // stage half A (k<256)  -- .cg: h written by other SMs, L1 stale
#pragma unroll
        for (int it = 0; it < 8; ++it) {
            int c = tid + it * 256;
            int bs = c >> 6;
            int kq = c & 63;
            float4 v = __ldcg((const float4*)&hsrc[(size_t)bs * HH + kq * 4]);
            *(float4*)&hsm[bs * HSTRIDE + kq * 4] = v;
        }
        __syncthreads();

        // issue half-B loads into registers (overlap with compute i=0,1)
        float4 tB[8];
#pragma unroll
        for (int it = 0; it < 8; ++it) {
            int c = tid + it * 256;
            int bs = c >> 6;
            int kq = 64 + (c & 63);
            tB[it] = __ldcg((const float4*)&hsrc[(size_t)bs * HH + kq * 4]);
        }

        unsigned long long acc[3][2][8];
#pragma unroll
        for (int g = 0; g < 3; ++g)
#pragma unroll
            for (int q = 0; q < 2; ++q)
#pragma unroll
                for (int t = 0; t < 8; ++t) acc[g][q][t] = 0ULL;

#define COMPUTE_I(i)                                                          \
        {                                                                     \
            const int kof = 4 * lane + 128 * (i);                             \
            ulonglong2 wv[6];                                                 \
            _Pragma("unroll")                                                 \
            for (int rr = 0; rr < 6; ++rr) {                                  \
                int gg = rr >> 1, jq = rr & 1;                                \
                wv[rr] = *(const ulonglong2*)&wsm[(gg*4 + jg*2 + jq)*HH + kof];\
            }                                                                 \
            _Pragma("unroll")                                                 \
            for (int bt = 0; bt < 8; ++bt) {                                  \
                ulonglong2 hv =                                               \
                    *(const ulonglong2*)&hsm[(bg*8 + bt)*HSTRIDE + kof];      \
                _Pragma("unroll")                                             \
                for (int rr = 0; rr < 6; ++rr) {                              \
                    int gg = rr >> 1, jq = rr & 1;                            \
                    asm("fma.rn.f32x2 %0, %1, %2, %0;"                        \
                        : "+l"(acc[gg][jq][bt]) : "l"(wv[rr].x), "l"(hv.x));  \
                    asm("fma.rn.f32x2 %0, %1, %2, %0;"                        \
                        : "+l"(acc[gg][jq][bt]) : "l"(wv[rr].y), "l"(hv.y));  \
                }                                                             \
            }                                                                 \
        }

        COMPUTE_I(0)
        COMPUTE_I(1)

        // store half B, then compute on it
#pragma unroll
        for (int it = 0; it < 8; ++it) {
            int c = tid + it * 256;
            int bs = c >> 6;
            int kq = 64 + (c & 63);
            *(float4*)&hsm[bs * HSTRIDE + kq * 4] = tB[it];
        }
        __syncthreads();

        COMPUTE_I(2)
        COMPUTE_I(3)
#undef COMPUTE_I

        // ---- unpack + cross-lane reduce via smem transpose ----
#pragma unroll
        for (int g = 0; g < 3; ++g)
#pragma unroll
            for (int q = 0; q < 2; ++q)
#pragma unroll
                for (int t = 0; t < 8; ++t) {
                    float2 f = *(float2*)&acc[g][q][t];
                    red[(w * 48 + (g * 16 + q * 8 + t)) * 33 + lane] = f.x + f.y;
                }
        __syncwarp();

        if (lane < 16) {
            float sum0 = 0.f, sum1 = 0.f, sum2 = 0.f;
            int base0 = (w * 48 + 0 * 16 + lane) * 33;
            int base1 = (w * 48 + 1 * 16 + lane) * 33;
            int base2 = (w * 48 + 2 * 16 + lane) * 33;
#pragma unroll
            for (int i = 0; i < 32; ++i) {
                sum0 += red[base0 + i];
                sum1 += red[base1 + i];
                sum2 += red[base2 + i];
            }
            float hold = hsm[b * HSTRIDE + j];
            float r  = 1.f / (1.f + __expf(-(xr + sum0)));
            float z  = 1.f / (1.f + __expf(-(xz + sum1)));
            float hc = tanhf(xh + r * sum2);
            float hn = (1.f - z) * hc + z * hold;
            hdst[(size_t)b * HH + j] = hn;
            hs_out[(size_t)(s * BB + b) * HH + j] = hn;
            if (s == SS - 1 && hfin) hfin[(size_t)b * HH + j] = hn;
        }

        // ---- grid barrier (sense reversal; all 128 blocks resident) ----
        __threadfence();
        __syncthreads();
        if (tid == 0) {
            unsigned ns = local_sense ^ 1u;
            if (atomicAdd(&g_cnt, 1u) == NBLK - 1) {
                g_cnt = 0;
                __threadfence();
                g_sense = ns;
            } else {
                while (g_sense != ns) { }
            }
        }
        local_sense ^= 1u;
        __syncthreads();
    }
}

// ------------------------------ driver ----------------------------------
extern "C" void kernel_launch(void* const* d_in, const int* in_sizes, int n_in,
                              void* d_out, int out_size)
{
    const int*   inputs = (const int*)d_in[0];
    const float* hidden = (const float*)d_in[1];
    const float* emb    = (const float*)d_in[2];
    const float* Wir    = (const float*)d_in[3];
    const float* bir    = (const float*)d_in[4];
    const float* Wiz    = (const float*)d_in[5];
    const float* biz    = (const float*)d_in[6];
    const float* Wih    = (const float*)d_in[7];
    const float* bih    = (const float*)d_in[8];
    const float* Whr    = (const float*)d_in[9];
    const float* Whz    = (const float*)d_in[10];
    const float* Whh    = (const float*)d_in[11];
    const float* Wout   = (const float*)d_in[12];
    const float* bout   = (const float*)d_in[13];
    float* out = (float*)d_out;

    float *px, *py, *pg, *ph;
    cudaGetSymbolAddress((void**)&px, g_x);
    cudaGetSymbolAddress((void**)&py, g_y);
    cudaGetSymbolAddress((void**)&pg, g_gates);
    cudaGetSymbolAddress((void**)&ph, g_h);

    const size_t logits_elems = (size_t)SB * VV;
    float* hfin_base = nullptr;
    if ((size_t)out_size >= logits_elems + (size_t)LL * BB * HH)
        hfin_base = out + logits_elems;

    const int smem_scan = (BB * HSTRIDE + 12 * HH + 8 * 48 * 33) * sizeof(float);
    cudaFuncSetAttribute(gru_scan_kernel,
                         cudaFuncAttributeMaxDynamicSharedMemorySize, smem_scan);

    // 1) embedding
    embed_kernel<<<SB, 128>>>(inputs, emb, px);

    const size_t CHNK = (size_t)SB * HH;
    for (int l = 0; l < LL; ++l) {
        float* in   = (l == 0) ? px : py;
        float* outb = (l == 0) ? py : px;

        // 2) fused input projections
        dim3 gProj(EE / 128, SB / 128, 3);
        sgemm_nt_bias3<<<gProj, 256>>>(
            in,
            Wir + (size_t)l * HH * EE, Wiz + (size_t)l * HH * EE, Wih + (size_t)l * HH * EE,
            bir + l * HH, biz + l * HH, bih + l * HH,
            pg + 0 * CHNK, pg + 1 * CHNK, pg + 2 * CHNK,
            SB, HH, EE);

        // 3) persistent scan over all 64 steps
        gru_scan_kernel<<<NBLK, 256, smem_scan>>>(
            pg,
            Whr + (size_t)l * HH * HH,
            Whz + (size_t)l * HH * HH,
            Whh + (size_t)l * HH * HH,
            hidden + (size_t)l * BB * HH,
            ph, outb,
            hfin_base ? hfin_base + (size_t)l * BB * HH : nullptr);
    }

    // 4) logits GEMM via tf32 tensor cores
    dim3 gLog(VV / 128, SB / 128);
    gemm_tf32_nt_bias<<<gLog, 128>>>(px, Wout, bout, out, SB, VV, EE);
}

// round 5
// speedup vs baseline: 2.2832x; 1.0586x over previous
#include <cuda_runtime.h>
#include <math.h>

#define SS 64
#define BB 32
#define HH 512
#define EE 512
#define VV 32000
#define LL 2
#define SB (SS*BB)   // 2048
#define NBLK 128
#define HSTRIDE 520  // 512 + 8 pad (16B-aligned rows)

// -------- scratch (no allocation allowed; device globals instead) --------
__device__ float g_x[SB*HH];
__device__ float g_y[SB*HH];
__device__ float g_gates[3*SB*HH];
__device__ unsigned g_cnt;            // zero-init
__device__ volatile unsigned g_sense; // zero-init; 64 flips/launch -> returns to 0

// ---------------------------- embedding ---------------------------------
__global__ void embed_kernel(const int* __restrict__ inputs,
                             const float* __restrict__ emb,
                             float* __restrict__ out)
{
    int row = blockIdx.x;
    int tok = inputs[row];
    const float4* src = (const float4*)(emb + (size_t)tok * EE);
    float4* dst = (float4*)(out + (size_t)row * EE);
    dst[threadIdx.x] = src[threadIdx.x];
}

// ------------------ tf32 tensor-core GEMM body ---------------------------
__device__ __forceinline__ unsigned f2tf(float x)
{
    unsigned r;
    asm("cvt.rna.tf32.f32 %0, %1;" : "=r"(r) : "f"(x));
    return r;
}

__device__ __forceinline__ void gemm_tf32_body(
    unsigned* __restrict__ As, unsigned* __restrict__ Bs,   // each 2*128*16
    const float* __restrict__ A, const float* __restrict__ W,
    const float* __restrict__ bias, float* __restrict__ C,
    int M, int N, int K)
{
    const int tid  = threadIdx.x;
    const int lane = tid & 31;
    const int warp = tid >> 5;
    const int wm = (warp >> 1) * 64;
    const int wn = (warp & 1) * 64;
    const int m0 = blockIdx.y * 128;
    const int n0 = blockIdx.x * 128;
    const int fr = lane >> 2;
    const int fc = lane & 3;
    const int cm  = tid >> 2;
    const int cc2 = tid & 3;

    float acc[4][8][4];
#pragma unroll
    for (int mt = 0; mt < 4; ++mt)
#pragma unroll
        for (int nt = 0; nt < 8; ++nt)
#pragma unroll
            for (int q = 0; q < 4; ++q) acc[mt][nt][q] = 0.f;

    float4 ra[4], rb[4];

#define LD_STAGE(k0)                                                          \
    {                                                                         \
        _Pragma("unroll")                                                     \
        for (int i = 0; i < 4; ++i) {                                         \
            int m = i * 32 + cm;                                              \
            ra[i] = *(const float4*)&A[(size_t)(m0 + m) * K + (k0) + cc2*4];  \
            rb[i] = *(const float4*)&W[(size_t)(n0 + m) * K + (k0) + cc2*4];  \
        }                                                                     \
    }

#define ST_STAGE(buf)                                                         \
    {                                                                         \
        _Pragma("unroll")                                                     \
        for (int i = 0; i < 4; ++i) {                                         \
            int m = i * 32 + cm;                                              \
            int off = (buf) * 2048 + m * 16 + ((cc2 ^ (m & 3)) << 2);         \
            uint4 ua; ua.x = f2tf(ra[i].x); ua.y = f2tf(ra[i].y);             \
            ua.z = f2tf(ra[i].z); ua.w = f2tf(ra[i].w);                       \
            uint4 ub; ub.x = f2tf(rb[i].x); ub.y = f2tf(rb[i].y);             \
            ub.z = f2tf(rb[i].z); ub.w = f2tf(rb[i].w);                       \
            *(uint4*)&As[off] = ua;                                           \
            *(uint4*)&Bs[off] = ub;                                           \
        }                                                                     \
    }

    LD_STAGE(0);
    ST_STAGE(0);
    __syncthreads();

    const int nstages = K / 16;
    for (int s = 0; s < nstages; ++s) {
        const int buf = s & 1;
        if (s + 1 < nstages) LD_STAGE((s + 1) * 16);

#pragma unroll
        for (int k8 = 0; k8 < 2; ++k8) {
            unsigned af[4][4], bf[8][2];
#pragma unroll
            for (int mt = 0; mt < 4; ++mt) {
                int r1 = wm + mt * 16 + fr;
                int r2 = r1 + 8;
                af[mt][0] = As[buf*2048 + r1*16 + (((k8*2+0) ^ (r1&3)) << 2) + fc];
                af[mt][1] = As[buf*2048 + r2*16 + (((k8*2+0) ^ (r2&3)) << 2) + fc];
                af[mt][2] = As[buf*2048 + r1*16 + (((k8*2+1) ^ (r1&3)) << 2) + fc];
                af[mt][3] = As[buf*2048 + r2*16 + (((k8*2+1) ^ (r2&3)) << 2) + fc];
            }
#pragma unroll
            for (int nt = 0; nt < 8; ++nt) {
                int n = wn + nt * 8 + fr;
                bf[nt][0] = Bs[buf*2048 + n*16 + (((k8*2+0) ^ (n&3)) << 2) + fc];
                bf[nt][1] = Bs[buf*2048 + n*16 + (((k8*2+1) ^ (n&3)) << 2) + fc];
            }
#pragma unroll
            for (int mt = 0; mt < 4; ++mt)
#pragma unroll
                for (int nt = 0; nt < 8; ++nt) {
                    asm volatile(
                        "mma.sync.aligned.m16n8k8.row.col.f32.tf32.tf32.f32 "
                        "{%0,%1,%2,%3}, {%4,%5,%6,%7}, {%8,%9}, {%0,%1,%2,%3};"
                        : "+f"(acc[mt][nt][0]), "+f"(acc[mt][nt][1]),
                          "+f"(acc[mt][nt][2]), "+f"(acc[mt][nt][3])
                        : "r"(af[mt][0]), "r"(af[mt][1]),
                          "r"(af[mt][2]), "r"(af[mt][3]),
                          "r"(bf[nt][0]), "r"(bf[nt][1]));
                }
        }
        if (s + 1 < nstages) ST_STAGE(buf ^ 1);
        __syncthreads();
    }
#undef LD_STAGE
#undef ST_STAGE

#pragma unroll
    for (int mt = 0; mt < 4; ++mt) {
        int row = m0 + wm + mt * 16 + fr;
#pragma unroll
        for (int nt = 0; nt < 8; ++nt) {
            int col = n0 + wn + nt * 8 + fc * 2;
            float bv0 = bias[col], bv1 = bias[col + 1];
            float2 v0; v0.x = acc[mt][nt][0] + bv0; v0.y = acc[mt][nt][1] + bv1;
            float2 v1; v1.x = acc[mt][nt][2] + bv0; v1.y = acc[mt][nt][3] + bv1;
            *(float2*)&C[(size_t)row * N + col] = v0;
            *(float2*)&C[(size_t)(row + 8) * N + col] = v1;
        }
    }
}

__global__ __launch_bounds__(128) void gemm_tf32_nt_bias(
    const float* __restrict__ A, const float* __restrict__ W,
    const float* __restrict__ bias, float* __restrict__ C,
    int M, int N, int K)
{
    __shared__ unsigned As[2 * 2048];
    __shared__ unsigned Bs[2 * 2048];
    gemm_tf32_body(As, Bs, A, W, bias, C, M, N, K);
}

// gate-fused variant for input projections (blockIdx.z picks gate)
__global__ __launch_bounds__(128) void gemm_tf32_nt_bias3(
    const float* __restrict__ A,
    const float* __restrict__ W0, const float* __restrict__ W1, const float* __restrict__ W2,
    const float* __restrict__ b0, const float* __restrict__ b1, const float* __restrict__ b2,
    float* __restrict__ C0, float* __restrict__ C1, float* __restrict__ C2,
    int M, int N, int K)
{
    __shared__ unsigned As[2 * 2048];
    __shared__ unsigned Bs[2 * 2048];
    const float* W    = (blockIdx.z == 0) ? W0 : (blockIdx.z == 1) ? W1 : W2;
    const float* bias = (blockIdx.z == 0) ? b0 : (blockIdx.z == 1) ? b1 : b2;
    float* C          = (blockIdx.z == 0) ? C0 : (blockIdx.z == 1) ? C1 : C2;
    gemm_tf32_body(As, Bs, A, W, bias, C, M, N, K);
}

// ------------------ persistent GRU scan v2 -------------------------------
// 128 blocks x 512 threads (16 warps = 4 jl x 4 bg). Block owns j in
// [4*bid, 4*bid+4). Warp (jl,bg): j = 4*bid+jl, b in [8*bg, 8*bg+8).
// Weight rows (Wr,Wz,Wh)[j] hoisted into registers ONCE (invariant over all
// 64 steps). h staged to smem via cp.async.cg each step. h chain lives in
// hs_out itself (hs_out[s-1] -> hs_out[s]); grid barrier between steps.
__device__ __forceinline__ void fma2(unsigned long long& a,
                                     unsigned long long x, unsigned long long h)
{
    asm("fma.rn.f32x2 %0, %1, %2, %0;" : "+l"(a) : "l"(x), "l"(h));
}

__global__ __launch_bounds__(512, 1) void gru_scan_kernel(
    const float* __restrict__ gates,   // [3][SB][HH]
    const float* __restrict__ Wr,
    const float* __restrict__ Wz,
    const float* __restrict__ Wh,
    const float* __restrict__ h0,      // [BB][HH]
    float* __restrict__ hs_out,        // [SS][BB][HH]
    float* __restrict__ hfin)          // [BB][HH] or null
{
    extern __shared__ float sm[];
    float* hsm = sm;                       // [32][HSTRIDE]
    float* red = sm + BB * HSTRIDE;        // [16][24][33]

    const int tid  = threadIdx.x;
    const int lane = tid & 31;
    const int w    = tid >> 5;
    const int jl   = w >> 2;               // 0..3
    const int bg   = w & 3;                // 0..3 (8 b each)
    const int bid  = blockIdx.x;
    const int j    = bid * 4 + jl;

    // hoist this warp's 3 weight rows into registers (16 floats/lane/row)
    ulonglong2 wv[3][4];
    {
        const float* Wrow0 = Wr + (size_t)j * HH;
        const float* Wrow1 = Wz + (size_t)j * HH;
        const float* Wrow2 = Wh + (size_t)j * HH;
#pragma unroll
        for (int i = 0; i < 4; ++i) {
            int kof = 4 * lane + 128 * i;
            wv[0][i] = *(const ulonglong2*)&Wrow0[kof];
            wv[1][i] = *(const ulonglong2*)&Wrow1[kof];
            wv[2][i] = *(const ulonglong2*)&Wrow2[kof];
        }
    }

    unsigned local_sense = 0;

    for (int s = 0; s < SS; ++s) {
        const float* hsrc = (s == 0) ? h0 : hs_out + (size_t)(s - 1) * BB * HH;
        float* hdst = hs_out + (size_t)s * BB * HH;

        // gate prefetch (only output lanes need it)
        float xr = 0.f, xz = 0.f, xh = 0.f;
        if (lane < 8) {
            int b = bg * 8 + lane;
            size_t idx = (size_t)(s * BB + b) * HH + j;
            xr = __ldcg(&gates[idx]);
            xz = __ldcg(&gates[(size_t)SB * HH + idx]);
            xh = __ldcg(&gates[(size_t)2 * SB * HH + idx]);
        }

        // stage h[32][512] into smem via cp.async.cg (bypass L1: cross-SM data)
#pragma unroll
        for (int it = 0; it < 8; ++it) {
            int c = tid + it * 512;        // 0..4095 float4 chunks
            int bs = c >> 7;               // row
            int kq = c & 127;              // float4 within row
            unsigned dst = (unsigned)__cvta_generic_to_shared(
                &hsm[bs * HSTRIDE + kq * 4]);
            const float* src = hsrc + (size_t)bs * HH + kq * 4;
            asm volatile("cp.async.cg.shared.global [%0], [%1], 16;"
                         :: "r"(dst), "l"(src));
        }
        asm volatile("cp.async.commit_group;");
        asm volatile("cp.async.wait_group 0;");
        __syncthreads();

        // ---- dot products: 3 gates x 8 b, k split over 32 lanes x 16 ----
        unsigned long long acc[3][8];
#pragma unroll
        for (int g = 0; g < 3; ++g)
#pragma unroll
            for (int c = 0; c < 8; ++c) acc[g][c] = 0ULL;

#pragma unroll
        for (int i = 0; i < 4; ++i) {
            const int kof = 4 * lane + 128 * i;
#pragma unroll
            for (int c = 0; c < 8; ++c) {
                ulonglong2 hv =
                    *(const ulonglong2*)&hsm[(bg * 8 + c) * HSTRIDE + kof];
                fma2(acc[0][c], wv[0][i].x, hv.x);
                fma2(acc[0][c], wv[0][i].y, hv.y);
                fma2(acc[1][c], wv[1][i].x, hv.x);
                fma2(acc[1][c], wv[1][i].y, hv.y);
                fma2(acc[2][c], wv[2][i].x, hv.x);
                fma2(acc[2][c], wv[2][i].y, hv.y);
            }
        }

        // ---- cross-lane reduce via smem transpose ----
#pragma unroll
        for (int g = 0; g < 3; ++g)
#pragma unroll
            for (int c = 0; c < 8; ++c) {
                float2 f = *(float2*)&acc[g][c];
                red[(w * 24 + g * 8 + c) * 33 + lane] = f.x + f.y;
            }
        __syncwarp();

        if (lane < 8) {
            int b = bg * 8 + lane;
            float s0 = 0.f, s1 = 0.f, s2 = 0.f;
            int base0 = (w * 24 + 0 * 8 + lane) * 33;
            int base1 = (w * 24 + 1 * 8 + lane) * 33;
            int base2 = (w * 24 + 2 * 8 + lane) * 33;
#pragma unroll
            for (int i = 0; i < 32; ++i) {
                s0 += red[base0 + i];
                s1 += red[base1 + i];
                s2 += red[base2 + i];
            }
            float hold = hsm[b * HSTRIDE + j];
            float r  = 1.f / (1.f + __expf(-(xr + s0)));
            float z  = 1.f / (1.f + __expf(-(xz + s1)));
            float hc = tanhf(xh + r * s2);
            float hn = (1.f - z) * hc + z * hold;
            hdst[(size_t)b * HH + j] = hn;
            if (s == SS - 1 && hfin) hfin[(size_t)b * HH + j] = hn;
        }

        // ---- grid barrier (sense reversal; all 128 blocks resident) ----
        __threadfence();
        __syncthreads();
        if (tid == 0) {
            unsigned ns = local_sense ^ 1u;
            if (atomicAdd(&g_cnt, 1u) == NBLK - 1) {
                g_cnt = 0;
                __threadfence();
                g_sense = ns;
            } else {
                while (g_sense != ns) { }
            }
        }
        local_sense ^= 1u;
        __syncthreads();
    }
}

// ------------------------------ driver ----------------------------------
extern "C" void kernel_launch(void* const* d_in, const int* in_sizes, int n_in,
                              void* d_out, int out_size)
{
    const int*   inputs = (const int*)d_in[0];
    const float* hidden = (const float*)d_in[1];
    const float* emb    = (const float*)d_in[2];
    const float* Wir    = (const float*)d_in[3];
    const float* bir    = (const float*)d_in[4];
    const float* Wiz    = (const float*)d_in[5];
    const float* biz    = (const float*)d_in[6];
    const float* Wih    = (const float*)d_in[7];
    const float* bih    = (const float*)d_in[8];
    const float* Whr    = (const float*)d_in[9];
    const float* Whz    = (const float*)d_in[10];
    const float* Whh    = (const float*)d_in[11];
    const float* Wout   = (const float*)d_in[12];
    const float* bout   = (const float*)d_in[13];
    float* out = (float*)d_out;

    float *px, *py, *pg;
    cudaGetSymbolAddress((void**)&px, g_x);
    cudaGetSymbolAddress((void**)&py, g_y);
    cudaGetSymbolAddress((void**)&pg, g_gates);

    const size_t logits_elems = (size_t)SB * VV;
    float* hfin_base = nullptr;
    if ((size_t)out_size >= logits_elems + (size_t)LL * BB * HH)
        hfin_base = out + logits_elems;

    const int smem_scan = (BB * HSTRIDE + 16 * 24 * 33) * sizeof(float);
    cudaFuncSetAttribute(gru_scan_kernel,
                         cudaFuncAttributeMaxDynamicSharedMemorySize, smem_scan);

    // 1) embedding
    embed_kernel<<<SB, 128>>>(inputs, emb, px);

    const size_t CHNK = (size_t)SB * HH;
    for (int l = 0; l < LL; ++l) {
        float* in   = (l == 0) ? px : py;
        float* outb = (l == 0) ? py : px;

        // 2) fused input projections (tf32 tensor cores, gate = blockIdx.z)
        dim3 gProj(HH / 128, SB / 128, 3);   // (4, 16, 3)
        gemm_tf32_nt_bias3<<<gProj, 128>>>(
            in,
            Wir + (size_t)l * HH * EE, Wiz + (size_t)l * HH * EE, Wih + (size_t)l * HH * EE,
            bir + l * HH, biz + l * HH, bih + l * HH,
            pg + 0 * CHNK, pg + 1 * CHNK, pg + 2 * CHNK,
            SB, HH, EE);

        // 3) persistent scan over all 64 steps
        gru_scan_kernel<<<NBLK, 512, smem_scan>>>(
            pg,
            Whr + (size_t)l * HH * HH,
            Whz + (size_t)l * HH * HH,
            Whh + (size_t)l * HH * HH,
            hidden + (size_t)l * BB * HH,
            outb,
            hfin_base ? hfin_base + (size_t)l * BB * HH : nullptr);
    }

    // 4) logits GEMM via tf32 tensor cores
    dim3 gLog(VV / 128, SB / 128);
    gemm_tf32_nt_bias<<<gLog, 128>>>(px, Wout, bout, out, SB, VV, EE);
}